// round 6
// baseline (speedup 1.0000x reference)
#include <cuda_runtime.h>
#include <cuda_bf16.h>
#include <mma.h>

using namespace nvcuda;

// Problem constants
#define BB 16
#define NN 512
#define HH 16
#define DK 64
#define DM 1024
#define MTOT (BB * NN)   // 8192

// Scratch (allocation-free rule: __device__ globals)
__device__ float g_q[BB * HH * NN * DK];
__device__ float g_k[BB * HH * NN * DK];
__device__ float g_v[BB * HH * NN * DK];
__device__ float g_ctx[MTOT * DM];

__device__ __forceinline__ float t32(float x) { return wmma::__float_to_tf32(x); }

__device__ __forceinline__ void cp16(void* dst_smem, const void* src) {
    unsigned d = (unsigned)__cvta_generic_to_shared(dst_smem);
    asm volatile("cp.async.ca.shared.global [%0], [%1], 16;" :: "r"(d), "l"(src));
}
__device__ __forceinline__ void cp_commit() { asm volatile("cp.async.commit_group;"); }
__device__ __forceinline__ void cp_wait0()  { asm volatile("cp.async.wait_group 0;"); }

// ---------------------------------------------------------------------------
// Projection GEMM: Y = X @ W^T + bias
// Block tile 128x128, 8 warps, warp tile 64x32 (4x2 wmma frags), tf32 m16n16k8.
// K-chunk 16, smem double-buffered (one __syncthreads per chunk), register
// staging with tf32 pre-round (no per-fragment cvt loops).
// Epilogue staging ldm = 36 floats (144B, multiple of 16B as wmma requires —
// ldm 33 in the previous revision was UB and corrupted all outputs).
// SPLIT=true  -> Y as [B, H, N, DK] (tf32-rounded), SPLIT=false -> [8192,1024]
// ---------------------------------------------------------------------------
template <bool SPLIT>
__global__ void __launch_bounds__(256, 2) proj_kernel(
    const float* __restrict__ X, const float* __restrict__ W,
    const float* __restrict__ bvec, float* __restrict__ Y)
{
    // 2 buffers x (A 128x20 + B 128x20) = 10240 floats = 40KB
    __shared__ __align__(16) float sm[10240];

    const int tid = threadIdx.x;
    const int warp = tid >> 5;
    const int lane = tid & 31;
    const int wm = warp & 1;      // m strip of 64
    const int wn = warp >> 1;     // n strip of 32
    const int mBase = blockIdx.x * 128;
    const int nBase = blockIdx.y * 128;

    const int tr = tid >> 2;            // 0..63
    const int tc = (tid & 3) * 4;       // 0,4,8,12

    wmma::fragment<wmma::accumulator, 16, 16, 8, float> acc[4][2];
#pragma unroll
    for (int i = 0; i < 4; i++)
#pragma unroll
        for (int j = 0; j < 2; j++) wmma::fill_fragment(acc[i][j], 0.0f);

    float4 ra[2], rb[2];

#define LD_CHUNK(K0)                                                                 \
    {                                                                                \
        _Pragma("unroll")                                                            \
        for (int p = 0; p < 2; p++) {                                                \
            ra[p] = *((const float4*)&X[(size_t)(mBase + tr + p * 64) * DM + (K0) + tc]); \
            rb[p] = *((const float4*)&W[(size_t)(nBase + tr + p * 64) * DM + (K0) + tc]); \
        }                                                                            \
    }

#define ST_CHUNK(NB)                                                                 \
    {                                                                                \
        float* As_ = sm + (NB) * 5120;                                               \
        float* Bs_ = As_ + 2560;                                                     \
        _Pragma("unroll")                                                            \
        for (int p = 0; p < 2; p++) {                                                \
            float4 v = ra[p];                                                        \
            v.x = t32(v.x); v.y = t32(v.y); v.z = t32(v.z); v.w = t32(v.w);          \
            *((float4*)&As_[(tr + p * 64) * 20 + tc]) = v;                           \
            float4 w4 = rb[p];                                                       \
            w4.x = t32(w4.x); w4.y = t32(w4.y); w4.z = t32(w4.z); w4.w = t32(w4.w);  \
            *((float4*)&Bs_[(tr + p * 64) * 20 + tc]) = w4;                          \
        }                                                                            \
    }

    LD_CHUNK(0);
    ST_CHUNK(0);
    __syncthreads();

    for (int kc = 0; kc < 64; kc++) {
        if (kc < 63) LD_CHUNK((kc + 1) * 16);

        const float* As = sm + (kc & 1) * 5120;
        const float* Bs = As + 2560;
#pragma unroll
        for (int kk = 0; kk < 2; kk++) {
            wmma::fragment<wmma::matrix_a, 16, 16, 8, wmma::precision::tf32, wmma::row_major> a[4];
#pragma unroll
            for (int i = 0; i < 4; i++)
                wmma::load_matrix_sync(a[i], &As[(wm * 64 + i * 16) * 20 + kk * 8], 20);
            wmma::fragment<wmma::matrix_b, 16, 16, 8, wmma::precision::tf32, wmma::col_major> b[2];
#pragma unroll
            for (int j = 0; j < 2; j++)
                wmma::load_matrix_sync(b[j], &Bs[(wn * 32 + j * 16) * 20 + kk * 8], 20);
#pragma unroll
            for (int i = 0; i < 4; i++)
#pragma unroll
                for (int j = 0; j < 2; j++)
                    wmma::mma_sync(acc[i][j], a[i], b[j], acc[i][j]);
        }

        if (kc < 63) ST_CHUNK((kc + 1) & 1);
        __syncthreads();
    }
#undef LD_CHUNK
#undef ST_CHUNK

    // Epilogue: per fm-block of 16 rows, stage 16x32 through smem (ldm 36 =
    // 144B, a legal 16B multiple), add bias, remap, store.
    // Per-warp stage = 16*36 = 576 floats; 8 warps = 4608 <= 10240.
    float* stg = sm + warp * 576;
    const int n = nBase + wn * 32 + lane;
    const float bv = bvec[n];
#pragma unroll
    for (int fm = 0; fm < 4; fm++) {
        __syncwarp();
#pragma unroll
        for (int fn = 0; fn < 2; fn++)
            wmma::store_matrix_sync(&stg[fn * 16], acc[fm][fn], 36, wmma::mem_row_major);
        __syncwarp();
#pragma unroll
        for (int r = 0; r < 16; r++) {
            float v = stg[r * 36 + lane] + bv;
            int m = mBase + wm * 64 + fm * 16 + r;
            if (SPLIT) {
                int b = m >> 9, i = m & 511;
                int hh = n >> 6, d = n & 63;
                Y[(((size_t)(b * HH + hh)) * NN + i) * DK + d] = t32(v);
            } else {
                Y[(size_t)m * DM + n] = v;
            }
        }
    }
}

// ---------------------------------------------------------------------------
// Fused attention: per CTA = (b,h, q-tile of 64 rows), 128 threads (4 warps)
// Q/K/V arrive pre-rounded to tf32 -> no conversions anywhere.
// bias+mask tiles prefetched to smem via cp.async at tile start; the wait
// lands AFTER the S=QK^T MMA, hiding the 268MB bias stream's DRAM latency.
// Row sums in registers; one butterfly reduce at the end.
// ---------------------------------------------------------------------------
__global__ void __launch_bounds__(128) attn_kernel(
    const float* __restrict__ bias, const int* __restrict__ mask)
{
    extern __shared__ float smd[];
    float* Qs  = smd;                // 64 x 68
    float* Ks  = Qs + 64 * 68;       // 64 x 68
    float* Vs  = Ks + 64 * 68;       // 64 x 68
    float* Ss  = Vs + 64 * 68;       // 64 x 68
    float* Bsm = Ss + 64 * 68;       // 64 x 64 bias tile
    int*   Msm = (int*)(Bsm + 64 * 64);  // 64 x 64 mask tile

    const int bh = blockIdx.y;
    const int b = bh >> 4;
    const int h = bh & 15;
    const int q0 = blockIdx.x * 64;
    const int tid = threadIdx.x;
    const int warp = tid >> 5;
    const int lane = tid & 31;
    const int m0 = warp * 16;

    // Load Q tile (64x64), already tf32-rounded
    const float* qptr = g_q + ((size_t)bh * NN + q0) * DK;
#pragma unroll
    for (int p = 0; p < 8; p++) {
        int e = tid + p * 128;
        int r = e >> 4, c4 = e & 15;
        *((float4*)&Qs[r * 68 + c4 * 4]) = ((const float4*)qptr)[r * 16 + c4];
    }

    wmma::fragment<wmma::accumulator, 16, 16, 8, float> o_acc[4];
#pragma unroll
    for (int t = 0; t < 4; t++) wmma::fill_fragment(o_acc[t], 0.0f);

    float rsum[16];
#pragma unroll
    for (int r = 0; r < 16; r++) rsum[r] = 0.0f;

    __syncthreads();

    const float* bbase0 = bias + ((size_t)bh * NN + q0) * NN;
    const int*   mbase0 = mask + ((size_t)b * NN + q0) * NN;

    for (int kt = 0; kt < 8; kt++) {
        const int k0 = kt * 64;

        // 1) Prefetch bias + mask tiles (64x64 each) via cp.async
        {
            const float* bb = bbase0 + k0;
            const int*   mb = mbase0 + k0;
#pragma unroll
            for (int p = 0; p < 8; p++) {
                int c = tid + p * 128;           // 0..1023 16B-chunks
                int r = c >> 4, c4 = (c & 15) * 4;
                cp16(&Bsm[r * 64 + c4], &bb[(size_t)r * NN + c4]);
                cp16(&Msm[r * 64 + c4], &mb[(size_t)r * NN + c4]);
            }
            cp_commit();
        }

        // 2) Stage K/V tiles
        const float* kptr = g_k + ((size_t)bh * NN + k0) * DK;
        const float* vptr = g_v + ((size_t)bh * NN + k0) * DK;
#pragma unroll
        for (int p = 0; p < 8; p++) {
            int e = tid + p * 128;
            int r = e >> 4, c4 = e & 15;
            *((float4*)&Ks[r * 68 + c4 * 4]) = ((const float4*)kptr)[r * 16 + c4];
            *((float4*)&Vs[r * 68 + c4 * 4]) = ((const float4*)vptr)[r * 16 + c4];
        }
        __syncthreads();

        // 3) S strip (16 x 64) per warp — bias cp.async completes underneath
        {
            wmma::fragment<wmma::accumulator, 16, 16, 8, float> s_acc[4];
#pragma unroll
            for (int t = 0; t < 4; t++) wmma::fill_fragment(s_acc[t], 0.0f);
#pragma unroll
            for (int kk = 0; kk < 8; kk++) {
                wmma::fragment<wmma::matrix_a, 16, 16, 8, wmma::precision::tf32, wmma::row_major> a;
                wmma::load_matrix_sync(a, &Qs[m0 * 68 + kk * 8], 68);
#pragma unroll
                for (int jt = 0; jt < 4; jt++) {
                    wmma::fragment<wmma::matrix_b, 16, 16, 8, wmma::precision::tf32, wmma::col_major> bf;
                    wmma::load_matrix_sync(bf, &Ks[jt * 16 * 68 + kk * 8], 68);
                    wmma::mma_sync(s_acc[jt], a, bf, s_acc[jt]);
                }
            }
#pragma unroll
            for (int jt = 0; jt < 4; jt++)
                wmma::store_matrix_sync(&Ss[m0 * 68 + jt * 16], s_acc[jt], 68,
                                        wmma::mem_row_major);
        }

        // 4) Wait for bias/mask, block-wide visibility
        cp_wait0();
        __syncthreads();

        // 5) Epilogue from smem: scale, +bias, mask, exp; row sums in regs
        {
#pragma unroll
            for (int r = 0; r < 16; r++) {
#pragma unroll
                for (int hf = 0; hf < 2; hf++) {
                    const int col = lane + hf * 32;
                    float val = Ss[(m0 + r) * 68 + col] * 0.125f +
                                Bsm[(m0 + r) * 64 + col];
                    float p = (Msm[(m0 + r) * 64 + col] == 0) ? 0.0f : __expf(val);
                    p = t32(p);
                    Ss[(m0 + r) * 68 + col] = p;
                    rsum[r] += p;
                }
            }
        }
        __syncwarp();

        // 6) O += P @ V
#pragma unroll
        for (int kk = 0; kk < 8; kk++) {
            wmma::fragment<wmma::matrix_a, 16, 16, 8, wmma::precision::tf32, wmma::row_major> a;
            wmma::load_matrix_sync(a, &Ss[m0 * 68 + kk * 8], 68);
#pragma unroll
            for (int dt = 0; dt < 4; dt++) {
                wmma::fragment<wmma::matrix_b, 16, 16, 8, wmma::precision::tf32, wmma::row_major> bf;
                wmma::load_matrix_sync(bf, &Vs[(kk * 8) * 68 + dt * 16], 68);
                wmma::mma_sync(o_acc[dt], a, bf, o_acc[dt]);
            }
        }
        __syncthreads();   // protect Ks/Vs/Bsm/Msm before next tile
    }

    // Store O strip via smem, normalize by reduced row sums, write ctx
#pragma unroll
    for (int dt = 0; dt < 4; dt++)
        wmma::store_matrix_sync(&Ss[m0 * 68 + dt * 16], o_acc[dt], 68,
                                wmma::mem_row_major);
    __syncwarp();
    {
        float* obase = g_ctx + ((size_t)(b * NN) + q0 + m0) * DM + h * DK;
#pragma unroll
        for (int r = 0; r < 16; r++) {
            float s = rsum[r];
#pragma unroll
            for (int o = 16; o; o >>= 1) s += __shfl_xor_sync(0xffffffffu, s, o);
            const float inv = 1.0f / s;
#pragma unroll
            for (int hf = 0; hf < 2; hf++) {
                const int col = lane + hf * 32;
                obase[(size_t)r * DM + col] = Ss[(m0 + r) * 68 + col] * inv;
            }
        }
    }
}

// ---------------------------------------------------------------------------
extern "C" void kernel_launch(void* const* d_in, const int* in_sizes, int n_in,
                              void* d_out, int out_size)
{
    const float* query = (const float*)d_in[0];
    const float* key_  = (const float*)d_in[1];
    const float* value = (const float*)d_in[2];
    const float* abias = (const float*)d_in[3];
    const int*   mask  = (const int*)d_in[4];
    const float* Wq = (const float*)d_in[5];
    const float* bq = (const float*)d_in[6];
    const float* Wk = (const float*)d_in[7];
    const float* bk = (const float*)d_in[8];
    const float* Wv = (const float*)d_in[9];
    const float* bv = (const float*)d_in[10];
    const float* Wo = (const float*)d_in[11];
    const float* bo = (const float*)d_in[12];
    float* out = (float*)d_out;

    float *pq, *pk, *pv, *pctx;
    cudaGetSymbolAddress((void**)&pq, g_q);
    cudaGetSymbolAddress((void**)&pk, g_k);
    cudaGetSymbolAddress((void**)&pv, g_v);
    cudaGetSymbolAddress((void**)&pctx, g_ctx);

    // attn smem: 4*64*68 + 64*64 (bias) + 64*64 (mask) floats = 102400 B
    const int ATTN_SMEM = (4 * 64 * 68 + 2 * 64 * 64) * sizeof(float);
    cudaFuncSetAttribute(attn_kernel, cudaFuncAttributeMaxDynamicSharedMemorySize,
                         ATTN_SMEM);

    dim3 pgrid(MTOT / 128, DM / 128);
    proj_kernel<true><<<pgrid, 256>>>(query, Wq, bq, pq);
    proj_kernel<true><<<pgrid, 256>>>(key_, Wk, bk, pk);
    proj_kernel<true><<<pgrid, 256>>>(value, Wv, bv, pv);

    dim3 agrid(NN / 64, BB * HH);
    attn_kernel<<<agrid, 128, ATTN_SMEM>>>(abias, mask);

    proj_kernel<false><<<pgrid, 256>>>(pctx, Wo, bo, out);
}

// round 9
// speedup vs baseline: 2.0433x; 2.0433x over previous
#include <cuda_runtime.h>
#include <cuda_fp16.h>
#include <cuda_bf16.h>
#include <mma.h>

using namespace nvcuda;

// Problem constants
#define BB 16
#define NN 512
#define HH 16
#define DK 64
#define DM 1024
#define MTOT (BB * NN)   // 8192

// Scratch (allocation-free rule: __device__ globals)
__device__ float g_q[BB * HH * NN * DK];
__device__ float g_k[BB * HH * NN * DK];
__device__ float g_v[BB * HH * NN * DK];
__device__ float g_ctx[MTOT * DM];

__device__ __forceinline__ float t32(float x) { return wmma::__float_to_tf32(x); }

// ---------------------------------------------------------------------------
// Projection GEMM: Y = X @ W^T + bias   —   fp16 HMMA (m16n16k16)
// fp16 has the same 11-bit significand as tf32, so accuracy matches the
// passing tf32 version; HMMA fp16 runs at 2x the tf32 rate and halves the
// smem staging bytes.
// Block tile 128x128, 8 warps, warp tile 64x32 (4x2 frags), K-chunk 32,
// double-buffered smem (one __syncthreads per chunk), register staging.
// SPLIT=true  -> Y as [B, H, N, DK] (tf32-rounded), SPLIT=false -> [8192,1024]
// ---------------------------------------------------------------------------
template <bool SPLIT>
__global__ void __launch_bounds__(256, 2) proj_kernel(
    const float* __restrict__ X, const float* __restrict__ W,
    const float* __restrict__ bvec, float* __restrict__ Y)
{
    // 2 buffers x (A 128x40 + B 128x40) halves = 20480 halves = 40 KB
    __shared__ __align__(16) __half sm[20480];

    const int tid = threadIdx.x;
    const int warp = tid >> 5;
    const int lane = tid & 31;
    const int wm = warp & 1;      // m strip of 64
    const int wn = warp >> 1;     // n strip of 32
    const int mBase = blockIdx.x * 128;
    const int nBase = blockIdx.y * 128;

    wmma::fragment<wmma::accumulator, 16, 16, 16, float> acc[4][2];
#pragma unroll
    for (int i = 0; i < 4; i++)
#pragma unroll
        for (int j = 0; j < 2; j++) wmma::fill_fragment(acc[i][j], 0.0f);

    float4 ra[4], rbw[4];

    // Per-thread staging coords: u = p*256 + tid -> row 0..127, col4 0..28
    const int srow = tid >> 3;
    const int scol = (tid & 7) * 4;

#define LD_CHUNK(K0)                                                                   \
    {                                                                                  \
        _Pragma("unroll")                                                              \
        for (int p = 0; p < 4; p++) {                                                  \
            ra[p]  = *((const float4*)&X[(size_t)(mBase + srow + p * 32) * DM + (K0) + scol]); \
            rbw[p] = *((const float4*)&W[(size_t)(nBase + srow + p * 32) * DM + (K0) + scol]); \
        }                                                                              \
    }

#define ST_CHUNK(NB)                                                                   \
    {                                                                                  \
        __half* As_ = sm + (NB) * 10240;                                               \
        __half* Bs_ = As_ + 5120;                                                      \
        _Pragma("unroll")                                                              \
        for (int p = 0; p < 4; p++) {                                                  \
            __half2 a01 = __floats2half2_rn(ra[p].x, ra[p].y);                         \
            __half2 a23 = __floats2half2_rn(ra[p].z, ra[p].w);                         \
            *((__half2*)&As_[(srow + p * 32) * 40 + scol])     = a01;                  \
            *((__half2*)&As_[(srow + p * 32) * 40 + scol + 2]) = a23;                  \
            __half2 b01 = __floats2half2_rn(rbw[p].x, rbw[p].y);                       \
            __half2 b23 = __floats2half2_rn(rbw[p].z, rbw[p].w);                       \
            *((__half2*)&Bs_[(srow + p * 32) * 40 + scol])     = b01;                  \
            *((__half2*)&Bs_[(srow + p * 32) * 40 + scol + 2]) = b23;                  \
        }                                                                              \
    }

    LD_CHUNK(0);
    ST_CHUNK(0);
    __syncthreads();

    for (int kc = 0; kc < 32; kc++) {
        if (kc < 31) LD_CHUNK((kc + 1) * 32);

        const __half* As = sm + (kc & 1) * 10240;
        const __half* Bs = As + 5120;
#pragma unroll
        for (int kk = 0; kk < 2; kk++) {
            wmma::fragment<wmma::matrix_a, 16, 16, 16, __half, wmma::row_major> a[4];
#pragma unroll
            for (int i = 0; i < 4; i++)
                wmma::load_matrix_sync(a[i], &As[(wm * 64 + i * 16) * 40 + kk * 16], 40);
            wmma::fragment<wmma::matrix_b, 16, 16, 16, __half, wmma::col_major> b[2];
#pragma unroll
            for (int j = 0; j < 2; j++)
                wmma::load_matrix_sync(b[j], &Bs[(wn * 32 + j * 16) * 40 + kk * 16], 40);
#pragma unroll
            for (int i = 0; i < 4; i++)
#pragma unroll
                for (int j = 0; j < 2; j++)
                    wmma::mma_sync(acc[i][j], a[i], b[j], acc[i][j]);
        }

        if (kc < 31) ST_CHUNK((kc + 1) & 1);
        __syncthreads();
    }
#undef LD_CHUNK
#undef ST_CHUNK

    // Epilogue: per fm-block of 16 rows, stage 16x32 fp32 through smem
    // (ldm 36 floats = 144B, legal 16B multiple), add bias, remap, store.
    // Per-warp stage = 576 floats; 8 warps = 4608 floats = 18KB <= 40KB.
    float* stgAll = reinterpret_cast<float*>(sm);
    float* stg = stgAll + warp * 576;
    const int n = nBase + wn * 32 + lane;
    const float bv = bvec[n];
#pragma unroll
    for (int fm = 0; fm < 4; fm++) {
        __syncwarp();
#pragma unroll
        for (int fn = 0; fn < 2; fn++)
            wmma::store_matrix_sync(&stg[fn * 16], acc[fm][fn], 36, wmma::mem_row_major);
        __syncwarp();
#pragma unroll
        for (int r = 0; r < 16; r++) {
            float v = stg[r * 36 + lane] + bv;
            int m = mBase + wm * 64 + fm * 16 + r;
            if (SPLIT) {
                int b = m >> 9, i = m & 511;
                int hh = n >> 6, d = n & 63;
                Y[(((size_t)(b * HH + hh)) * NN + i) * DK + d] = t32(v);
            } else {
                Y[(size_t)m * DM + n] = v;
            }
        }
    }
}

// ---------------------------------------------------------------------------
// Fused attention (verified 429us version): per CTA = (b,h, 64 q-rows),
// 128 threads (4 warps). Q/K/V pre-rounded tf32 -> no cvts. Coalesced
// lane=col epilogue, register row sums, wmma tf32.
// ---------------------------------------------------------------------------
__global__ void __launch_bounds__(128, 3) attn_kernel(
    const float* __restrict__ bias, const int* __restrict__ mask)
{
    extern __shared__ float smd[];
    float* Qs = smd;               // 64 x 68
    float* Ks = Qs + 64 * 68;      // 64 x 68
    float* Vs = Ks + 64 * 68;      // 64 x 68
    float* Ss = Vs + 64 * 68;      // 64 x 68

    const int bh = blockIdx.y;
    const int b = bh >> 4;
    const int h = bh & 15;
    const int q0 = blockIdx.x * 64;
    const int tid = threadIdx.x;
    const int warp = tid >> 5;
    const int lane = tid & 31;
    const int m0 = warp * 16;

    const float* qptr = g_q + ((size_t)bh * NN + q0) * DK;
#pragma unroll
    for (int p = 0; p < 8; p++) {
        int e = tid + p * 128;
        int r = e >> 4, c4 = e & 15;
        *((float4*)&Qs[r * 68 + c4 * 4]) = ((const float4*)qptr)[r * 16 + c4];
    }

    wmma::fragment<wmma::accumulator, 16, 16, 8, float> o_acc[4];
#pragma unroll
    for (int t = 0; t < 4; t++) wmma::fill_fragment(o_acc[t], 0.0f);

    float rsum[16];
#pragma unroll
    for (int r = 0; r < 16; r++) rsum[r] = 0.0f;

    __syncthreads();

    for (int kt = 0; kt < 8; kt++) {
        const int k0 = kt * 64;
        const float* kptr = g_k + ((size_t)bh * NN + k0) * DK;
        const float* vptr = g_v + ((size_t)bh * NN + k0) * DK;
#pragma unroll
        for (int p = 0; p < 8; p++) {
            int e = tid + p * 128;
            int r = e >> 4, c4 = e & 15;
            *((float4*)&Ks[r * 68 + c4 * 4]) = ((const float4*)kptr)[r * 16 + c4];
            *((float4*)&Vs[r * 68 + c4 * 4]) = ((const float4*)vptr)[r * 16 + c4];
        }
        __syncthreads();

        {
            wmma::fragment<wmma::accumulator, 16, 16, 8, float> s_acc[4];
#pragma unroll
            for (int t = 0; t < 4; t++) wmma::fill_fragment(s_acc[t], 0.0f);
#pragma unroll
            for (int kk = 0; kk < 8; kk++) {
                wmma::fragment<wmma::matrix_a, 16, 16, 8, wmma::precision::tf32, wmma::row_major> a;
                wmma::load_matrix_sync(a, &Qs[m0 * 68 + kk * 8], 68);
#pragma unroll
                for (int jt = 0; jt < 4; jt++) {
                    wmma::fragment<wmma::matrix_b, 16, 16, 8, wmma::precision::tf32, wmma::col_major> bf;
                    wmma::load_matrix_sync(bf, &Ks[jt * 16 * 68 + kk * 8], 68);
                    wmma::mma_sync(s_acc[jt], a, bf, s_acc[jt]);
                }
            }
#pragma unroll
            for (int jt = 0; jt < 4; jt++)
                wmma::store_matrix_sync(&Ss[m0 * 68 + jt * 16], s_acc[jt], 68,
                                        wmma::mem_row_major);
        }
        __syncwarp();

        {
            const float* bbase = bias + ((size_t)bh * NN + (q0 + m0)) * NN + k0;
            const int* mbase = mask + ((size_t)b * NN + (q0 + m0)) * NN + k0;
#pragma unroll
            for (int r = 0; r < 16; r++) {
#pragma unroll
                for (int hf = 0; hf < 2; hf++) {
                    const int col = lane + hf * 32;
                    float val = Ss[(m0 + r) * 68 + col] * 0.125f +
                                bbase[(size_t)r * NN + col];
                    float p = (mbase[(size_t)r * NN + col] == 0) ? 0.0f : __expf(val);
                    p = t32(p);
                    Ss[(m0 + r) * 68 + col] = p;
                    rsum[r] += p;
                }
            }
        }
        __syncwarp();

#pragma unroll
        for (int kk = 0; kk < 8; kk++) {
            wmma::fragment<wmma::matrix_a, 16, 16, 8, wmma::precision::tf32, wmma::row_major> a;
            wmma::load_matrix_sync(a, &Ss[m0 * 68 + kk * 8], 68);
#pragma unroll
            for (int dt = 0; dt < 4; dt++) {
                wmma::fragment<wmma::matrix_b, 16, 16, 8, wmma::precision::tf32, wmma::row_major> bf;
                wmma::load_matrix_sync(bf, &Vs[(kk * 8) * 68 + dt * 16], 68);
                wmma::mma_sync(o_acc[dt], a, bf, o_acc[dt]);
            }
        }
        __syncthreads();
    }

#pragma unroll
    for (int dt = 0; dt < 4; dt++)
        wmma::store_matrix_sync(&Ss[m0 * 68 + dt * 16], o_acc[dt], 68,
                                wmma::mem_row_major);
    __syncwarp();
    {
        float* obase = g_ctx + ((size_t)(b * NN) + q0 + m0) * DM + h * DK;
#pragma unroll
        for (int r = 0; r < 16; r++) {
            float s = rsum[r];
#pragma unroll
            for (int o = 16; o; o >>= 1) s += __shfl_xor_sync(0xffffffffu, s, o);
            const float inv = 1.0f / s;
#pragma unroll
            for (int hf = 0; hf < 2; hf++) {
                const int col = lane + hf * 32;
                obase[(size_t)r * DM + col] = Ss[(m0 + r) * 68 + col] * inv;
            }
        }
    }
}

// ---------------------------------------------------------------------------
extern "C" void kernel_launch(void* const* d_in, const int* in_sizes, int n_in,
                              void* d_out, int out_size)
{
    const float* query = (const float*)d_in[0];
    const float* key_  = (const float*)d_in[1];
    const float* value = (const float*)d_in[2];
    const float* abias = (const float*)d_in[3];
    const int*   mask  = (const int*)d_in[4];
    const float* Wq = (const float*)d_in[5];
    const float* bq = (const float*)d_in[6];
    const float* Wk = (const float*)d_in[7];
    const float* bk = (const float*)d_in[8];
    const float* Wv = (const float*)d_in[9];
    const float* bv = (const float*)d_in[10];
    const float* Wo = (const float*)d_in[11];
    const float* bo = (const float*)d_in[12];
    float* out = (float*)d_out;

    float *pq, *pk, *pv, *pctx;
    cudaGetSymbolAddress((void**)&pq, g_q);
    cudaGetSymbolAddress((void**)&pk, g_k);
    cudaGetSymbolAddress((void**)&pv, g_v);
    cudaGetSymbolAddress((void**)&pctx, g_ctx);

    const int ATTN_SMEM = (4 * 64 * 68) * sizeof(float);  // 69632
    cudaFuncSetAttribute(attn_kernel, cudaFuncAttributeMaxDynamicSharedMemorySize,
                         ATTN_SMEM);

    dim3 pgrid(MTOT / 128, DM / 128);
    proj_kernel<true><<<pgrid, 256>>>(query, Wq, bq, pq);
    proj_kernel<true><<<pgrid, 256>>>(key_, Wk, bk, pk);
    proj_kernel<true><<<pgrid, 256>>>(value, Wv, bv, pv);

    dim3 agrid(NN / 64, BB * HH);
    attn_kernel<<<agrid, 128, ATTN_SMEM>>>(abias, mask);

    proj_kernel<false><<<pgrid, 256>>>(pctx, Wo, bo, out);
}

// round 10
// speedup vs baseline: 2.6045x; 1.2746x over previous
#include <cuda_runtime.h>
#include <cuda_fp16.h>
#include <cuda_bf16.h>
#include <mma.h>

using namespace nvcuda;

// Problem constants
#define BB 16
#define NN 512
#define HH 16
#define DK 64
#define DM 1024
#define MTOT (BB * NN)   // 8192

// Scratch (allocation-free rule: __device__ globals)
__device__ __half g_q[BB * HH * NN * DK];
__device__ __half g_k[BB * HH * NN * DK];
__device__ __half g_v[BB * HH * NN * DK];
__device__ float  g_ctx[MTOT * DM];

struct QKVArgs {
    const float* X[3];
    const float* W[3];
    const float* bv[3];
    __half*      Y[3];
};

// ---------------------------------------------------------------------------
// Merged QKV projection: grid.z picks (input, weight, bias, output).
// Y = X @ W^T + b, written head-split as [B, H, N, DK] in fp16.
// fp16 HMMA m16n16k16, block tile 128x128, 8 warps, warp tile 64x32,
// K-chunk 32, double-buffered smem, register staging.
// ---------------------------------------------------------------------------
__global__ void __launch_bounds__(256, 2) qkv_proj_kernel(QKVArgs args)
{
    __shared__ __align__(16) __half sm[20480];  // 40 KB

    const int z = blockIdx.z;
    const float* __restrict__ X = args.X[z];
    const float* __restrict__ W = args.W[z];
    const float* __restrict__ bvec = args.bv[z];
    __half* __restrict__ Y = args.Y[z];

    const int tid = threadIdx.x;
    const int warp = tid >> 5;
    const int lane = tid & 31;
    const int wm = warp & 1;
    const int wn = warp >> 1;
    const int mBase = blockIdx.x * 128;
    const int nBase = blockIdx.y * 128;

    wmma::fragment<wmma::accumulator, 16, 16, 16, float> acc[4][2];
#pragma unroll
    for (int i = 0; i < 4; i++)
#pragma unroll
        for (int j = 0; j < 2; j++) wmma::fill_fragment(acc[i][j], 0.0f);

    float4 ra[4], rbw[4];
    const int srow = tid >> 3;
    const int scol = (tid & 7) * 4;

#define LD_CHUNK(K0)                                                                   \
    {                                                                                  \
        _Pragma("unroll")                                                              \
        for (int p = 0; p < 4; p++) {                                                  \
            ra[p]  = *((const float4*)&X[(size_t)(mBase + srow + p * 32) * DM + (K0) + scol]); \
            rbw[p] = *((const float4*)&W[(size_t)(nBase + srow + p * 32) * DM + (K0) + scol]); \
        }                                                                              \
    }

#define ST_CHUNK(NB)                                                                   \
    {                                                                                  \
        __half* As_ = sm + (NB) * 10240;                                               \
        __half* Bs_ = As_ + 5120;                                                      \
        _Pragma("unroll")                                                              \
        for (int p = 0; p < 4; p++) {                                                  \
            *((__half2*)&As_[(srow + p * 32) * 40 + scol])     = __floats2half2_rn(ra[p].x, ra[p].y); \
            *((__half2*)&As_[(srow + p * 32) * 40 + scol + 2]) = __floats2half2_rn(ra[p].z, ra[p].w); \
            *((__half2*)&Bs_[(srow + p * 32) * 40 + scol])     = __floats2half2_rn(rbw[p].x, rbw[p].y); \
            *((__half2*)&Bs_[(srow + p * 32) * 40 + scol + 2]) = __floats2half2_rn(rbw[p].z, rbw[p].w); \
        }                                                                              \
    }

    LD_CHUNK(0);
    ST_CHUNK(0);
    __syncthreads();

    for (int kc = 0; kc < 32; kc++) {
        if (kc < 31) LD_CHUNK((kc + 1) * 32);

        const __half* As = sm + (kc & 1) * 10240;
        const __half* Bs = As + 5120;
#pragma unroll
        for (int kk = 0; kk < 2; kk++) {
            wmma::fragment<wmma::matrix_a, 16, 16, 16, __half, wmma::row_major> a[4];
#pragma unroll
            for (int i = 0; i < 4; i++)
                wmma::load_matrix_sync(a[i], &As[(wm * 64 + i * 16) * 40 + kk * 16], 40);
            wmma::fragment<wmma::matrix_b, 16, 16, 16, __half, wmma::col_major> b[2];
#pragma unroll
            for (int j = 0; j < 2; j++)
                wmma::load_matrix_sync(b[j], &Bs[(wn * 32 + j * 16) * 40 + kk * 16], 40);
#pragma unroll
            for (int i = 0; i < 4; i++)
#pragma unroll
                for (int j = 0; j < 2; j++)
                    wmma::mma_sync(acc[i][j], a[i], b[j], acc[i][j]);
        }

        if (kc < 31) ST_CHUNK((kc + 1) & 1);
        __syncthreads();
    }
#undef LD_CHUNK
#undef ST_CHUNK

    // Epilogue: stage 16x32 fp32 per warp (ldm 36 = 144B, legal), add bias,
    // write head-split fp16.
    float* stg = reinterpret_cast<float*>(sm) + warp * 576;
    const int n = nBase + wn * 32 + lane;
    const float bv = bvec[n];
#pragma unroll
    for (int fm = 0; fm < 4; fm++) {
        __syncwarp();
#pragma unroll
        for (int fn = 0; fn < 2; fn++)
            wmma::store_matrix_sync(&stg[fn * 16], acc[fm][fn], 36, wmma::mem_row_major);
        __syncwarp();
#pragma unroll
        for (int r = 0; r < 16; r++) {
            float v = stg[r * 36 + lane] + bv;
            int m = mBase + wm * 64 + fm * 16 + r;
            int b = m >> 9, i = m & 511;
            int hh = n >> 6, d = n & 63;
            Y[(((size_t)(b * HH + hh)) * NN + i) * DK + d] = __float2half(v);
        }
    }
}

// ---------------------------------------------------------------------------
// Output projection: out = ctx @ Wo^T + bo, fp32 in/out. Same GEMM shape.
// ---------------------------------------------------------------------------
__global__ void __launch_bounds__(256, 2) out_proj_kernel(
    const float* __restrict__ X, const float* __restrict__ W,
    const float* __restrict__ bvec, float* __restrict__ Y)
{
    __shared__ __align__(16) __half sm[20480];

    const int tid = threadIdx.x;
    const int warp = tid >> 5;
    const int lane = tid & 31;
    const int wm = warp & 1;
    const int wn = warp >> 1;
    const int mBase = blockIdx.x * 128;
    const int nBase = blockIdx.y * 128;

    wmma::fragment<wmma::accumulator, 16, 16, 16, float> acc[4][2];
#pragma unroll
    for (int i = 0; i < 4; i++)
#pragma unroll
        for (int j = 0; j < 2; j++) wmma::fill_fragment(acc[i][j], 0.0f);

    float4 ra[4], rbw[4];
    const int srow = tid >> 3;
    const int scol = (tid & 7) * 4;

#define LD_CHUNK(K0)                                                                   \
    {                                                                                  \
        _Pragma("unroll")                                                              \
        for (int p = 0; p < 4; p++) {                                                  \
            ra[p]  = *((const float4*)&X[(size_t)(mBase + srow + p * 32) * DM + (K0) + scol]); \
            rbw[p] = *((const float4*)&W[(size_t)(nBase + srow + p * 32) * DM + (K0) + scol]); \
        }                                                                              \
    }

#define ST_CHUNK(NB)                                                                   \
    {                                                                                  \
        __half* As_ = sm + (NB) * 10240;                                               \
        __half* Bs_ = As_ + 5120;                                                      \
        _Pragma("unroll")                                                              \
        for (int p = 0; p < 4; p++) {                                                  \
            *((__half2*)&As_[(srow + p * 32) * 40 + scol])     = __floats2half2_rn(ra[p].x, ra[p].y); \
            *((__half2*)&As_[(srow + p * 32) * 40 + scol + 2]) = __floats2half2_rn(ra[p].z, ra[p].w); \
            *((__half2*)&Bs_[(srow + p * 32) * 40 + scol])     = __floats2half2_rn(rbw[p].x, rbw[p].y); \
            *((__half2*)&Bs_[(srow + p * 32) * 40 + scol + 2]) = __floats2half2_rn(rbw[p].z, rbw[p].w); \
        }                                                                              \
    }

    LD_CHUNK(0);
    ST_CHUNK(0);
    __syncthreads();

    for (int kc = 0; kc < 32; kc++) {
        if (kc < 31) LD_CHUNK((kc + 1) * 32);

        const __half* As = sm + (kc & 1) * 10240;
        const __half* Bs = As + 5120;
#pragma unroll
        for (int kk = 0; kk < 2; kk++) {
            wmma::fragment<wmma::matrix_a, 16, 16, 16, __half, wmma::row_major> a[4];
#pragma unroll
            for (int i = 0; i < 4; i++)
                wmma::load_matrix_sync(a[i], &As[(wm * 64 + i * 16) * 40 + kk * 16], 40);
            wmma::fragment<wmma::matrix_b, 16, 16, 16, __half, wmma::col_major> b[2];
#pragma unroll
            for (int j = 0; j < 2; j++)
                wmma::load_matrix_sync(b[j], &Bs[(wn * 32 + j * 16) * 40 + kk * 16], 40);
#pragma unroll
            for (int i = 0; i < 4; i++)
#pragma unroll
                for (int j = 0; j < 2; j++)
                    wmma::mma_sync(acc[i][j], a[i], b[j], acc[i][j]);
        }

        if (kc < 31) ST_CHUNK((kc + 1) & 1);
        __syncthreads();
    }
#undef LD_CHUNK
#undef ST_CHUNK

    float* stg = reinterpret_cast<float*>(sm) + warp * 576;
    const int n = nBase + wn * 32 + lane;
    const float bv = bvec[n];
#pragma unroll
    for (int fm = 0; fm < 4; fm++) {
        __syncwarp();
#pragma unroll
        for (int fn = 0; fn < 2; fn++)
            wmma::store_matrix_sync(&stg[fn * 16], acc[fm][fn], 36, wmma::mem_row_major);
        __syncwarp();
#pragma unroll
        for (int r = 0; r < 16; r++) {
            float v = stg[r * 36 + lane] + bv;
            int m = mBase + wm * 64 + fm * 16 + r;
            Y[(size_t)m * DM + n] = v;
        }
    }
}

// ---------------------------------------------------------------------------
// Fused attention, fp16 MMA version: per CTA = (b,h, 64 q-rows), 4 warps.
// Q/K/V are fp16 in global (written by proj). S accumulated fp32, epilogue
// (scale, +bias, mask, exp) writes P as fp16; PV in fp16 m16n16k16.
// smem 54.3KB -> 4 CTAs/SM.
// ---------------------------------------------------------------------------
__global__ void __launch_bounds__(128, 4) attn_kernel(
    const float* __restrict__ bias, const int* __restrict__ mask)
{
    extern __shared__ __align__(16) char smraw[];
    __half* Qh = (__half*)smraw;                 // 64 x 72
    __half* Kh = Qh + 64 * 72;                   // 64 x 72
    __half* Vh = Kh + 64 * 72;                   // 64 x 72
    __half* Ph = Vh + 64 * 72;                   // 64 x 72
    float*  Ss = (float*)(Ph + 64 * 72);         // 64 x 68

    const int bh = blockIdx.y;
    const int b = bh >> 4;
    const int h = bh & 15;
    const int q0 = blockIdx.x * 64;
    const int tid = threadIdx.x;
    const int warp = tid >> 5;
    const int lane = tid & 31;
    const int m0 = warp * 16;

    // Load Q tile (64x64 half) — 512 uint4, 4 per thread
    const __half* qptr = g_q + ((size_t)bh * NN + q0) * DK;
#pragma unroll
    for (int p = 0; p < 4; p++) {
        int e = tid + p * 128;
        int r = e >> 3, c8 = e & 7;
        *((uint4*)&Qh[r * 72 + c8 * 8]) = ((const uint4*)qptr)[r * 8 + c8];
    }

    wmma::fragment<wmma::accumulator, 16, 16, 16, float> o_acc[4];
#pragma unroll
    for (int t = 0; t < 4; t++) wmma::fill_fragment(o_acc[t], 0.0f);

    float rsum[16];
#pragma unroll
    for (int r = 0; r < 16; r++) rsum[r] = 0.0f;

    __syncthreads();

    for (int kt = 0; kt < 8; kt++) {
        const int k0 = kt * 64;
        const __half* kptr = g_k + ((size_t)bh * NN + k0) * DK;
        const __half* vptr = g_v + ((size_t)bh * NN + k0) * DK;
#pragma unroll
        for (int p = 0; p < 4; p++) {
            int e = tid + p * 128;
            int r = e >> 3, c8 = e & 7;
            *((uint4*)&Kh[r * 72 + c8 * 8]) = ((const uint4*)kptr)[r * 8 + c8];
            *((uint4*)&Vh[r * 72 + c8 * 8]) = ((const uint4*)vptr)[r * 8 + c8];
        }
        __syncthreads();

        // S strip (16 x 64) per warp, fp16 m16n16k16 (4 k-steps)
        {
            wmma::fragment<wmma::accumulator, 16, 16, 16, float> s_acc[4];
#pragma unroll
            for (int t = 0; t < 4; t++) wmma::fill_fragment(s_acc[t], 0.0f);
#pragma unroll
            for (int kk = 0; kk < 4; kk++) {
                wmma::fragment<wmma::matrix_a, 16, 16, 16, __half, wmma::row_major> a;
                wmma::load_matrix_sync(a, &Qh[m0 * 72 + kk * 16], 72);
#pragma unroll
                for (int jt = 0; jt < 4; jt++) {
                    wmma::fragment<wmma::matrix_b, 16, 16, 16, __half, wmma::col_major> bf;
                    wmma::load_matrix_sync(bf, &Kh[(jt * 16) * 72 + kk * 16], 72);
                    wmma::mma_sync(s_acc[jt], a, bf, s_acc[jt]);
                }
            }
#pragma unroll
            for (int jt = 0; jt < 4; jt++)
                wmma::store_matrix_sync(&Ss[m0 * 68 + jt * 16], s_acc[jt], 68,
                                        wmma::mem_row_major);
        }
        __syncwarp();

        // Epilogue: lane = column (coalesced bias/mask), rows looped.
        // scale, +bias, mask, exp -> P (fp16), row sums in registers.
        {
            const float* bbase = bias + ((size_t)bh * NN + (q0 + m0)) * NN + k0;
            const int* mbase = mask + ((size_t)b * NN + (q0 + m0)) * NN + k0;
#pragma unroll
            for (int r = 0; r < 16; r++) {
#pragma unroll
                for (int hf = 0; hf < 2; hf++) {
                    const int col = lane + hf * 32;
                    float val = Ss[(m0 + r) * 68 + col] * 0.125f +
                                bbase[(size_t)r * NN + col];
                    float p = (mbase[(size_t)r * NN + col] == 0) ? 0.0f : __expf(val);
                    __half ph = __float2half(p);
                    Ph[(m0 + r) * 72 + col] = ph;
                    rsum[r] += __half2float(ph);
                }
            }
        }
        __syncwarp();

        // O += P @ V  (fp16 m16n16k16, 4 k-steps)
#pragma unroll
        for (int kk = 0; kk < 4; kk++) {
            wmma::fragment<wmma::matrix_a, 16, 16, 16, __half, wmma::row_major> a;
            wmma::load_matrix_sync(a, &Ph[m0 * 72 + kk * 16], 72);
#pragma unroll
            for (int dt = 0; dt < 4; dt++) {
                wmma::fragment<wmma::matrix_b, 16, 16, 16, __half, wmma::row_major> bf;
                wmma::load_matrix_sync(bf, &Vh[(kk * 16) * 72 + dt * 16], 72);
                wmma::mma_sync(o_acc[dt], a, bf, o_acc[dt]);
            }
        }
        __syncthreads();   // protect Kh/Vh before next tile's staging
    }

    // Store O strip via Ss, normalize by reduced row sums, write ctx fp32
#pragma unroll
    for (int dt = 0; dt < 4; dt++)
        wmma::store_matrix_sync(&Ss[m0 * 68 + dt * 16], o_acc[dt], 68,
                                wmma::mem_row_major);
    __syncwarp();
    {
        float* obase = g_ctx + ((size_t)(b * NN) + q0 + m0) * DM + h * DK;
#pragma unroll
        for (int r = 0; r < 16; r++) {
            float s = rsum[r];
#pragma unroll
            for (int o = 16; o; o >>= 1) s += __shfl_xor_sync(0xffffffffu, s, o);
            const float inv = 1.0f / s;
#pragma unroll
            for (int hf = 0; hf < 2; hf++) {
                const int col = lane + hf * 32;
                obase[(size_t)r * DM + col] = Ss[(m0 + r) * 68 + col] * inv;
            }
        }
    }
}

// ---------------------------------------------------------------------------
extern "C" void kernel_launch(void* const* d_in, const int* in_sizes, int n_in,
                              void* d_out, int out_size)
{
    const float* query = (const float*)d_in[0];
    const float* key_  = (const float*)d_in[1];
    const float* value = (const float*)d_in[2];
    const float* abias = (const float*)d_in[3];
    const int*   mask  = (const int*)d_in[4];
    const float* Wq = (const float*)d_in[5];
    const float* bq = (const float*)d_in[6];
    const float* Wk = (const float*)d_in[7];
    const float* bk = (const float*)d_in[8];
    const float* Wv = (const float*)d_in[9];
    const float* bv = (const float*)d_in[10];
    const float* Wo = (const float*)d_in[11];
    const float* bo = (const float*)d_in[12];
    float* out = (float*)d_out;

    __half *pq, *pk, *pv;
    float *pctx;
    cudaGetSymbolAddress((void**)&pq, g_q);
    cudaGetSymbolAddress((void**)&pk, g_k);
    cudaGetSymbolAddress((void**)&pv, g_v);
    cudaGetSymbolAddress((void**)&pctx, g_ctx);

    // attn smem: 4*(64*72)*2 (Q,K,V,P half) + 64*68*4 (S fp32) = 54272 B
    const int ATTN_SMEM = 4 * (64 * 72) * 2 + 64 * 68 * 4;
    cudaFuncSetAttribute(attn_kernel, cudaFuncAttributeMaxDynamicSharedMemorySize,
                         ATTN_SMEM);

    QKVArgs args;
    args.X[0] = query; args.X[1] = key_; args.X[2] = value;
    args.W[0] = Wq;    args.W[1] = Wk;   args.W[2] = Wv;
    args.bv[0] = bq;   args.bv[1] = bk;  args.bv[2] = bv;
    args.Y[0] = pq;    args.Y[1] = pk;   args.Y[2] = pv;

    dim3 qkvgrid(MTOT / 128, DM / 128, 3);
    qkv_proj_kernel<<<qkvgrid, 256>>>(args);

    dim3 agrid(NN / 64, BB * HH);
    attn_kernel<<<agrid, 128, ATTN_SMEM>>>(abias, mask);

    dim3 pgrid(MTOT / 128, DM / 128);
    out_proj_kernel<<<pgrid, 256>>>(pctx, Wo, bo, out);
}